// round 17
// baseline (speedup 1.0000x reference)
#include <cuda_runtime.h>
#include <cstdint>

namespace {
constexpr int EMBD  = 64;
constexpr int HID   = 128;
constexpr int NN    = 4096;
constexpr int P1    = 2047;
constexpr int STEPS = 4094;
constexpr int TPB   = 256;
constexpr int NBT   = NN / TPB;     // 16 neighbors per thread
constexpr int CSL   = 6;            // private candidate slots per thread

struct SmemB {                       // phase-2 kernel SMEM
    float xe[EMBD];
    float hbuf[2][HID];
    float hs[2][16];
    float partial[TPB];
    float gact[64];
    float W_emb_s[EMBD * 2];
    float b_emb_s[EMBD];
    unsigned wm[16];
    float2 cand[2][CSL][TPB];
    unsigned long long mb[2];
};
} // namespace

__device__ float g_xih[(size_t)P1 * 512];      // precomputed x@W_ih (permuted)
__device__ float g_hist[(size_t)STEPS * HID];  // h history (both phases)
__device__ float g_c[HID];                     // cell state handoff
__device__ float g_hprev[HID];                 // h state handoff
__device__ float g_pos[4];                     // pcx, pcy, ppx, ppy handoff

// ---------------- PTX helpers ----------------
__device__ __forceinline__ unsigned ctarank() {
    unsigned r; asm("mov.u32 %0, %%cluster_ctarank;" : "=r"(r)); return r;
}
__device__ __forceinline__ void cluster_sync_() {
    asm volatile("barrier.cluster.arrive.aligned;" ::: "memory");
    asm volatile("barrier.cluster.wait.aligned;" ::: "memory");
}
__device__ __forceinline__ unsigned mapa_(unsigned la, unsigned rank) {
    unsigned ra;
    asm("mapa.shared::cluster.u32 %0, %1, %2;" : "=r"(ra) : "r"(la), "r"(rank));
    return ra;
}
__device__ __forceinline__ void mbar_init(unsigned a, unsigned cnt) {
    asm volatile("mbarrier.init.shared.b64 [%0], %1;" :: "r"(a), "r"(cnt) : "memory");
}
__device__ __forceinline__ void mbar_expect(unsigned a, unsigned bytes) {
    asm volatile("mbarrier.arrive.expect_tx.shared.b64 _, [%0], %1;"
                 :: "r"(a), "r"(bytes) : "memory");
}
__device__ __forceinline__ void mbar_wait(unsigned a, unsigned parity) {
    asm volatile(
        "{\n\t.reg .pred P;\n"
        "WL%=:\n\t"
        "mbarrier.try_wait.parity.acquire.cluster.shared::cta.b64 P, [%0], %1, 0x989680;\n\t"
        "@P bra WD%=;\n\t"
        "bra WL%=;\n"
        "WD%=:\n\t}"
        :: "r"(a), "r"(parity) : "memory");
}
__device__ __forceinline__ void st_async_f32(unsigned raddr, float v, unsigned rmbar) {
    asm volatile(
        "st.async.shared::cluster.mbarrier::complete_tx::bytes.b32 [%0], %1, [%2];"
        :: "r"(raddr), "r"(__float_as_uint(v)), "r"(rmbar) : "memory");
}
__device__ __forceinline__ void st_async_b64(unsigned raddr, unsigned long long v,
                                             unsigned rmbar) {
    asm volatile(
        "st.async.shared::cluster.mbarrier::complete_tx::bytes.b64 [%0], %1, [%2];"
        :: "r"(raddr), "l"(v), "r"(rmbar) : "memory");
}
__device__ __forceinline__ float reduce16(float v) {
#pragma unroll
    for (int o = 8; o > 0; o >>= 1) v += __shfl_xor_sync(0xFFFFu, v, o);
    return v;
}
__device__ __forceinline__ float fsig(float x) {
    return __fdividef(1.0f, 1.0f + __expf(-x));
}
__device__ __forceinline__ float ftanh(float x) {
    return __fdividef(2.0f, 1.0f + __expf(-2.0f * x)) - 1.0f;
}

// occupancy test: exact JAX linspace edge semantics
__device__ __forceinline__ void occ_point(float x, float y, float cx, float cy,
                                          unsigned& lo, unsigned& hi) {
    if (fabsf(x - cx) < 1.6f && fabsf(y - cy) < 1.6f) {
        int ix = -1, iy = -1;
#pragma unroll
        for (int c = 0; c < 6; c++) {
            float ex0 = cx + (0.5f * c - 1.5f);
            float ex1 = cx + (0.5f * c - 1.0f);
            if (x > ex0 && x < ex1) ix = c;
            float ey0 = cy + (0.5f * c - 1.5f);
            float ey1 = cy + (0.5f * c - 1.0f);
            if (y > ey0 && y < ey1) iy = c;
        }
        if (ix >= 0 && iy >= 0) {
            int b = ix * 6 + iy;
            if (b < 32) lo |= 1u << b; else hi |= 1u << (b - 32);
        }
    }
}

// ---------------- Kernel A: phase-1 x@W_ih precompute (parallel) ----------------
__global__ void __launch_bounds__(TPB) olstm_pre(
    const float* __restrict__ observed, const float* __restrict__ other,
    const float* __restrict__ W_emb, const float* __restrict__ b_emb,
    const float* __restrict__ W_ih)
{
    __shared__ __align__(16) float x100[100];
    __shared__ unsigned wlo[8], whi[8];
    const int t = blockIdx.x;
    const int tid = threadIdx.x;
    const float px = observed[t * 2],       py = observed[t * 2 + 1];
    const float cx = observed[(t + 1) * 2], cy = observed[(t + 1) * 2 + 1];
    const float dx = cx - px, dy = cy - py;

    const float2* oth2 = reinterpret_cast<const float2*>(other);
    unsigned lo = 0u, hi = 0u;
    for (int i = 0; i < NBT; i++) {
        float2 p = oth2[(size_t)(t + 1) * NN + i * TPB + tid];
        occ_point(p.x, p.y, cx, cy, lo, hi);
    }
    lo = __reduce_or_sync(0xffffffffu, lo);
    hi = __reduce_or_sync(0xffffffffu, hi);
    if ((tid & 31) == 0) { wlo[tid >> 5] = lo; whi[tid >> 5] = hi; }
    if (tid < EMBD) {
        float e = fmaf(dx, W_emb[tid * 2], fmaf(dy, W_emb[tid * 2 + 1], b_emb[tid]));
        x100[tid] = e > 0.0f ? e : 0.0f;
    }
    __syncthreads();
    if (tid >= 64 && tid < 100) {
        int b = tid - 64;
        unsigned fm = (b < 32)
            ? (wlo[0]|wlo[1]|wlo[2]|wlo[3]|wlo[4]|wlo[5]|wlo[6]|wlo[7])
            : (whi[0]|whi[1]|whi[2]|whi[3]|whi[4]|whi[5]|whi[6]|whi[7]);
        x100[tid] = ((fm >> (b & 31)) & 1u) ? 1.0f : 0.0f;
    }
    __syncthreads();

    const float4* xq = reinterpret_cast<const float4*>(x100);
    const float4* w0 = reinterpret_cast<const float4*>(W_ih + (size_t)tid * 100);
    const float4* w1 = reinterpret_cast<const float4*>(W_ih + (size_t)(tid + 256) * 100);
    float a0 = 0.0f, a1 = 0.0f;
#pragma unroll
    for (int i = 0; i < 25; i++) {
        float4 xx = xq[i], wa = w0[i], wb = w1[i];
        a0 = fmaf(wa.x, xx.x, a0); a0 = fmaf(wa.y, xx.y, a0);
        a0 = fmaf(wa.z, xx.z, a0); a0 = fmaf(wa.w, xx.w, a0);
        a1 = fmaf(wb.x, xx.x, a1); a1 = fmaf(wb.y, xx.y, a1);
        a1 = fmaf(wb.z, xx.z, a1); a1 = fmaf(wb.w, xx.w, a1);
    }
    // layout: idx = ((gr>>4)&7)*64 + (gr>>7)*16 + (gr&15)
    const int r0 = tid, r1 = tid + 256;
    g_xih[(size_t)t * 512 + ((r0 >> 4) & 7) * 64 + (r0 >> 7) * 16 + (r0 & 15)] = a0;
    g_xih[(size_t)t * 512 + ((r1 >> 4) & 7) * 64 + (r1 >> 7) * 16 + (r1 & 15)] = a1;
}

// ---------------- Kernel B1: phase 1, 2-CTA cluster x 512 threads ----------------
// Thread (m = tid>>1, p = tid&1) owns K-half p of local gate row m (256 rows/CTA).
// Gate row gr = (m>>6)*128 + rk*64 + (m&63). 64 reg weights per thread.
// Exchange: threads 0..127 (j = tid&63, rdest = tid>>6) send h[rk*64+j] to rank
// rdest; 128 f32 tx per destination barrier = 512 bytes.
__global__ void __cluster_dims__(2, 1, 1) __launch_bounds__(512, 1)
olstm_p1(const float* __restrict__ observed,
         const float* __restrict__ b_ih,  const float* __restrict__ W_hh,
         const float* __restrict__ b_hh,
         const float* __restrict__ W_out, const float* __restrict__ b_out)
{
    __shared__ __align__(16) float hbuf[2][HID];
    __shared__ float partial[512];
    __shared__ float gact[256];
    __shared__ __align__(8) unsigned long long mb_s[2];

    const int tid = threadIdx.x;
    const unsigned lane = tid & 31;
    const int warp = tid >> 5;
    const unsigned rk = ctarank();
    const int m = tid >> 1, p = tid & 1;
    const int gr = (m >> 6) * 128 + (int)rk * 64 + (m & 63);

    float w[64];
#pragma unroll
    for (int i = 0; i < 64; i++) w[i] = W_hh[(size_t)gr * HID + p * 64 + i];

    float bs_g = 0.0f;
    if (tid < 256) {
        int g2 = (tid >> 6) * 128 + (int)rk * 64 + (tid & 63);
        bs_g = b_ih[g2] + b_hh[g2];
    }
    const int xidx = ((gr >> 4) & 7) * 64 + (gr >> 7) * 16 + (gr & 15);

    float woA[4] = {0,0,0,0}, woB[4] = {0,0,0,0};     // warp0: W_out rows 0,1
    if (warp == 0) {
#pragma unroll
        for (int i = 0; i < 4; i++) {
            woA[i] = W_out[lane + 32 * i];
            woB[i] = W_out[HID + lane + 32 * i];
        }
    }
    const float bo0 = b_out[0], bo1 = b_out[1];

    for (int i = tid; i < 2 * HID; i += 512) hbuf[0][i] = 0.0f;  // both buffers
    const unsigned mb0  = (unsigned)__cvta_generic_to_shared(&mb_s[0]);
    const unsigned mb1  = mb0 + 8;
    const unsigned la_h = (unsigned)__cvta_generic_to_shared(&hbuf[0][0]);
    if (tid == 0) { mbar_init(mb0, 1); mbar_init(mb1, 1); mbar_expect(mb0, 512); }
    __syncthreads();
    cluster_sync_();

    float cst = 0.0f;                                  // threads 0..127 (x2 repl)
    float pcx = 0.0f, pcy = 0.0f, ppx = 0.0f, ppy = 0.0f;  // warp0 lane0
    float xcur = (p == 0) ? g_xih[xidx] : 0.0f;
    float xnext = 0.0f;

    for (int t = 0; t < P1; t++) {
        const int cur = t & 1, nxt = cur ^ 1;
        const unsigned mb_c = (t & 1) ? mb1 : mb0;
        const unsigned mb_n = (t & 1) ? mb0 : mb1;
        if (tid == 0) mbar_expect(mb_n, 512);
        if (p == 0 && t + 1 < P1)
            xnext = g_xih[(size_t)(t + 1) * 512 + xidx];

        // GEMV: 64 h-cols from SMEM x 64 reg weights, 4 accumulators
        const float4* hq = reinterpret_cast<const float4*>(hbuf[cur] + p * 64);
        float a0 = xcur, a1 = 0.0f, a2 = 0.0f, a3 = 0.0f;
#pragma unroll
        for (int i = 0; i < 16; i++) {
            float4 hh = hq[i];
            a0 = fmaf(w[4 * i],     hh.x, a0); a1 = fmaf(w[4 * i + 1], hh.y, a1);
            a2 = fmaf(w[4 * i + 2], hh.z, a2); a3 = fmaf(w[4 * i + 3], hh.w, a3);
        }
        partial[p * 256 + m] = (a0 + a1) + (a2 + a3);
        __syncthreads();

        if (tid < 256) {
            float gv = bs_g + partial[tid] + partial[256 + tid];
            gact[tid] = ((tid >> 6) == 2) ? ftanh(gv) : fsig(gv);
        }
        if (tid < 256) asm volatile("bar.sync 1, 256;" ::: "memory");
        if (tid < 128) {
            const int j = tid & 63, rdest = tid >> 6;
            float ig = gact[j],       fg = gact[64 + j];
            float gg = gact[128 + j], og = gact[192 + j];
            float cN = fmaf(fg, cst, ig * gg);
            cst = cN;
            float hN = og * ftanh(cN);
            unsigned dst = la_h + (unsigned)((nxt * HID + (int)rk * 64 + j) * 4);
            st_async_f32(mapa_(dst, (unsigned)rdest), hN,
                         mapa_(mb_c, (unsigned)rdest));
            if (rdest == 0) g_hist[(size_t)t * HID + rk * 64 + j] = hN;
        }
        mbar_wait(mb_c, (t >> 1) & 1);
        // last two steps: positions for the phase-2 carry (warp0)
        if (t >= P1 - 2 && warp == 0) {
            float u0 = 0.0f, u1 = 0.0f;
#pragma unroll
            for (int i = 0; i < 4; i++) {
                float hv = hbuf[nxt][lane + 32 * i];
                u0 = fmaf(hv, woA[i], u0);
                u1 = fmaf(hv, woB[i], u1);
            }
#pragma unroll
            for (int o = 16; o > 0; o >>= 1) {
                u0 += __shfl_xor_sync(0xffffffffu, u0, o);
                u1 += __shfl_xor_sync(0xffffffffu, u1, o);
            }
            if (lane == 0) {
                ppx = pcx; ppy = pcy;
                pcx = observed[(t + 1) * 2]     + u0 + bo0;
                pcy = observed[(t + 1) * 2 + 1] + u1 + bo1;
            }
        }
        xcur = xnext;
    }

    // ---- state handoff (stream order makes these visible to olstm_p2) ----
    if (tid < 64) g_c[rk * 64 + tid] = cst;            // rdest==0 copies
    if (tid < HID) g_hprev[tid] = hbuf[(P1 - 1) & 1 ? 0 : 1][tid];  // nxt of last step
    if (rk == 0 && tid == 0) {
        g_pos[0] = pcx; g_pos[1] = pcy; g_pos[2] = ppx; g_pos[3] = ppy;
    }
}

// ---------------- Kernel B2 helper (R16: gates + 128-thread fanout) ----------
__device__ __forceinline__ void gates_and_send(SmemB* s, int tid, unsigned rk,
                                               int nxt, unsigned mb_c,
                                               unsigned la_h, unsigned la_hs,
                                               float& cst, float bs_g,
                                               float wo0, float wo1, float* hist) {
    if (tid < 128) {
        if (tid < 64) {
            float gv = bs_g + s->partial[tid] + s->partial[tid + 64]
                     + s->partial[tid + 128] + s->partial[tid + 192];
            s->gact[tid] = (tid < 32 || tid >= 48) ? fsig(gv) : ftanh(gv);
        }
        asm volatile("bar.sync 1, 128;" ::: "memory");
        const int j = tid & 15, r = tid >> 4;
        float ig = s->gact[j],      fg = s->gact[16 + j];
        float gg = s->gact[32 + j], og = s->gact[48 + j];
        float cN = fmaf(fg, cst, ig * gg);
        cst = cN;
        float hN = og * ftanh(cN);
        unsigned dst = la_h + (unsigned)((nxt * HID + (int)rk * 16 + j) * 4);
        st_async_f32(mapa_(dst, (unsigned)r), hN, mapa_(mb_c, (unsigned)r));
        if (tid < 16) {
            float s0 = reduce16(hN * wo0);
            float s1 = reduce16(hN * wo1);
            if (tid < 8) {
                unsigned long long pk =
                    (((unsigned long long)__float_as_uint(s1)) << 32)
                    | (unsigned long long)__float_as_uint(s0);
                unsigned sdst = la_hs + (unsigned)((nxt * 16 + (int)rk * 2) * 4);
                st_async_b64(mapa_(sdst, (unsigned)tid), pk,
                             mapa_(mb_c, (unsigned)tid));
            }
            hist[rk * 16 + tid] = hN;
        }
    }
}

// ---------------- Kernel B2: phase 2, 8-CTA cluster x 256 (R16 structure) ------
__global__ void __cluster_dims__(8, 1, 1) __launch_bounds__(TPB, 1)
olstm_p2(const float* __restrict__ other,
         const float* __restrict__ W_emb, const float* __restrict__ b_emb,
         const float* __restrict__ W_ih,  const float* __restrict__ b_ih,
         const float* __restrict__ W_hh,  const float* __restrict__ b_hh,
         const float* __restrict__ W_out, const float* __restrict__ b_out,
         float* __restrict__ out)
{
    __shared__ __align__(16) SmemB s;
    const int tid = threadIdx.x;
    const unsigned lane = tid & 31;
    const int warp = tid >> 5;
    const unsigned rk = ctarank();
    const int m = tid & 63, part = tid >> 6;
    const int gr = (m >> 4) * HID + (int)rk * 16 + (m & 15);

    float w[48], wocc[9];
#pragma unroll
    for (int i = 0; i < 16; i++) w[i] = W_ih[(size_t)gr * 100 + part * 16 + i];
#pragma unroll
    for (int i = 0; i < 32; i++) w[16 + i] = W_hh[(size_t)gr * 128 + part * 32 + i];
#pragma unroll
    for (int i = 0; i < 9; i++)  wocc[i] = W_ih[(size_t)gr * 100 + 64 + part * 9 + i];

    float bs_g = 0.0f;
    if (tid < 64) {
        int g2 = (tid >> 4) * HID + (int)rk * 16 + (tid & 15);
        bs_g = b_ih[g2] + b_hh[g2];
    }
    float wo0 = 0.0f, wo1 = 0.0f;
    if (tid < 16) {
        wo0 = W_out[rk * 16 + tid];
        wo1 = W_out[HID + rk * 16 + tid];
    }
    const float bo0 = b_out[0], bo1 = b_out[1];

    // rigorous one-step drift bound
    float Rx, Ry;
    {
        float a = 0.0f, b = 0.0f;
        for (int k = (int)lane; k < HID; k += 32) {
            float v0 = W_out[k], v1 = W_out[HID + k];
            a = fmaf(v0, v0, a); b = fmaf(v1, v1, b);
        }
#pragma unroll
        for (int o = 16; o > 0; o >>= 1) {
            a += __shfl_xor_sync(0xffffffffu, a, o);
            b += __shfl_xor_sync(0xffffffffu, b, o);
        }
        Rx = 1.6f + sqrtf(a) * 11.3137086f + fabsf(bo0) + 0.01f;
        Ry = 1.6f + sqrtf(b) * 11.3137086f + fabsf(bo1) + 0.01f;
    }

    for (int i = tid; i < EMBD * 2; i += TPB) s.W_emb_s[i] = W_emb[i];
    if (tid < EMBD) s.b_emb_s[tid] = b_emb[tid];
    if (tid < HID) { s.hbuf[0][tid] = g_hprev[tid]; s.hbuf[1][tid] = 0.0f; }
    if (tid < 32) s.hs[0][tid] = 0.0f;
    if (tid < 16) s.wm[tid] = 0u;

    const unsigned mb0   = (unsigned)__cvta_generic_to_shared(&s.mb[0]);
    const unsigned mb1   = mb0 + 8;
    const unsigned la_h  = (unsigned)__cvta_generic_to_shared(&s.hbuf[0][0]);
    const unsigned la_hs = (unsigned)__cvta_generic_to_shared(&s.hs[0][0]);
    if (tid == 0) { mbar_init(mb0, 1); mbar_init(mb1, 1); mbar_expect(mb0, 576); }
    __syncthreads();
    cluster_sync_();

    const float2* oth2 = reinterpret_cast<const float2*>(other);
    float2 nb[NBT];
    int ccnt = 0;
    float cst = (tid < 128) ? g_c[rk * 16 + (tid & 15)] : 0.0f;
    float pcx = g_pos[0], pcy = g_pos[1], ppx = g_pos[2], ppy = g_pos[3];

    // ---- bootstrap shortlist for u=0 (row P1+1, center pc_P1) + prefetch ----
    {
#pragma unroll
        for (int i = 0; i < NBT; i++)
            nb[i] = oth2[(size_t)(P1 + 1) * NN + i * TPB + tid];
#pragma unroll
        for (int i = 0; i < NBT; i++) {
            if (fabsf(nb[i].x - pcx) < Rx && fabsf(nb[i].y - pcy) < Ry) {
                if (ccnt < CSL) s.cand[0][ccnt][tid] = nb[i];
                ccnt++;
            }
        }
#pragma unroll
        for (int i = 0; i < NBT; i++)
            nb[i] = oth2[(size_t)(P1 + 2) * NN + i * TPB + tid];
    }
    __syncthreads();

    // ======================= phase 2 loop (u = t - P1) =======================
    for (int u = 0; u < STEPS - P1; u++) {
        const int t = P1 + u;
        const int cur = u & 1, nxt = cur ^ 1;
        const unsigned mb_c = (u & 1) ? mb1 : mb0;
        const unsigned mb_n = (u & 1) ? mb0 : mb1;
        const int bc = u & 1;
        if (tid == 0) mbar_expect(mb_n, 576u);

        const float cx = pcx, cy = pcy;
        const float dx = pcx - ppx, dy = pcy - ppy;
        unsigned lo = 0u, hi = 0u;
        if (ccnt <= CSL) {
#pragma unroll
            for (int k = 0; k < CSL; k++) {
                if (k < ccnt) {
                    float2 p = s.cand[bc][k][tid];
                    occ_point(p.x, p.y, cx, cy, lo, hi);
                }
            }
        } else {                                // deterministic overflow fallback
            for (int i = 0; i < NBT; i++) {
                float2 p = __ldg(&oth2[(size_t)(t + 1) * NN + i * TPB + tid]);
                occ_point(p.x, p.y, cx, cy, lo, hi);
            }
        }
        lo = __reduce_or_sync(0xffffffffu, lo);
        hi = __reduce_or_sync(0xffffffffu, hi);
        if (lane == 0) { s.wm[warp] = lo; s.wm[8 + warp] = hi; }
        if (tid < 64) {
            float e = fmaf(dx, s.W_emb_s[tid * 2],
                      fmaf(dy, s.W_emb_s[tid * 2 + 1], s.b_emb_s[tid]));
            s.xe[tid] = e > 0.0f ? e : 0.0f;
        }
        __syncthreads();

        const float4* hq = reinterpret_cast<const float4*>(s.hbuf[cur] + part * 32);
        const float4* eq = reinterpret_cast<const float4*>(s.xe + part * 16);
        float a0 = 0.0f, a1 = 0.0f, a2 = 0.0f, a3 = 0.0f;
#pragma unroll
        for (int i = 0; i < 4; i++) {
            float4 xx = eq[i];
            a0 = fmaf(w[4 * i],     xx.x, a0); a1 = fmaf(w[4 * i + 1], xx.y, a1);
            a2 = fmaf(w[4 * i + 2], xx.z, a2); a3 = fmaf(w[4 * i + 3], xx.w, a3);
        }
#pragma unroll
        for (int i = 0; i < 8; i++) {
            float4 hh = hq[i];
            a0 = fmaf(w[16 + 4 * i], hh.x, a0); a1 = fmaf(w[17 + 4 * i], hh.y, a1);
            a2 = fmaf(w[18 + 4 * i], hh.z, a2); a3 = fmaf(w[19 + 4 * i], hh.w, a3);
        }
        {
            const uint4* wmv = reinterpret_cast<const uint4*>(s.wm);
            uint4 A = wmv[0], B = wmv[1], C = wmv[2], D = wmv[3];
            unsigned flo = A.x|A.y|A.z|A.w|B.x|B.y|B.z|B.w;
            unsigned fhi = C.x|C.y|C.z|C.w|D.x|D.y|D.z|D.w;
            unsigned long long occm = (((unsigned long long)fhi << 32) | flo) >> (part * 9);
#pragma unroll
            for (int i = 0; i < 9; i++) {
                float xb = ((occm >> i) & 1ull) ? 1.0f : 0.0f;
                a0 = fmaf(wocc[i], xb, a0);
            }
        }
        s.partial[tid] = (a0 + a1) + (a2 + a3);
        __syncthreads();

        gates_and_send(&s, tid, rk, nxt, mb_c, la_h, la_hs, cst, bs_g, wo0, wo1,
                       g_hist + (size_t)t * HID);

        // build shortlist for u+1 (row t+2) + prefetch row t+3 (slack window)
        {
            ccnt = 0;
            const int nbuf = bc ^ 1;
#pragma unroll
            for (int i = 0; i < NBT; i++) {
                if (fabsf(nb[i].x - cx) < Rx && fabsf(nb[i].y - cy) < Ry) {
                    if (ccnt < CSL) s.cand[nbuf][ccnt][tid] = nb[i];
                    ccnt++;
                }
            }
            if (t + 2 < STEPS) {
#pragma unroll
                for (int i = 0; i < NBT; i++)
                    nb[i] = oth2[(size_t)(t + 3) * NN + i * TPB + tid];
            }
        }
        mbar_wait(mb_c, (u >> 1) & 1);

        // post-wait: n0/n1 from contiguous piggybacked partials
        {
            const float4* hv = reinterpret_cast<const float4*>(s.hs[nxt]);
            float4 v0 = hv[0], v1 = hv[1], v2 = hv[2], v3 = hv[3];
            float n0 = bo0 + ((v0.x + v0.z) + (v1.x + v1.z))
                           + ((v2.x + v2.z) + (v3.x + v3.z));
            float n1 = bo1 + ((v0.y + v0.w) + (v1.y + v1.w))
                           + ((v2.y + v2.w) + (v3.y + v3.w));
            ppx = pcx; ppy = pcy;
            pcx += n0; pcy += n1;
            if (rk == 0 && tid == 0) {
                out[(size_t)t * 5 + 0] = n0;
                out[(size_t)t * 5 + 1] = n1;
            }
        }
    }
}

// ---------------- Kernel C: output heads (parallel) ----------------
__global__ void __launch_bounds__(160) olstm_head(
    const float* __restrict__ W_out, const float* __restrict__ b_out,
    float* __restrict__ out)
{
    const int t = blockIdx.x;
    const int tid = threadIdx.x;
    const int j = tid >> 5;
    const unsigned lane = tid & 31;
    if (t >= P1 && j < 2) return;
    const float* h = g_hist + (size_t)t * HID;
    float v = 0.0f;
#pragma unroll
    for (int i = 0; i < 4; i++)
        v = fmaf(h[lane + 32 * i], W_out[j * HID + lane + 32 * i], v);
#pragma unroll
    for (int off = 16; off > 0; off >>= 1)
        v += __shfl_down_sync(0xffffffffu, v, off);
    if (lane == 0) out[(size_t)t * 5 + j] = v + b_out[j];
}

extern "C" void kernel_launch(void* const* d_in, const int* in_sizes, int n_in,
                              void* d_out, int out_size) {
    (void)in_sizes; (void)n_in; (void)out_size;
    const float* observed = (const float*)d_in[0];
    const float* other    = (const float*)d_in[1];
    const float* W_emb    = (const float*)d_in[2];
    const float* b_emb    = (const float*)d_in[3];
    const float* W_ih     = (const float*)d_in[4];
    const float* b_ih     = (const float*)d_in[5];
    const float* W_hh     = (const float*)d_in[6];
    const float* b_hh     = (const float*)d_in[7];
    const float* W_out    = (const float*)d_in[8];
    const float* b_out    = (const float*)d_in[9];
    float* out = (float*)d_out;

    olstm_pre<<<P1, TPB>>>(observed, other, W_emb, b_emb, W_ih);
    olstm_p1<<<2, 512>>>(observed, b_ih, W_hh, b_hh, W_out, b_out);
    olstm_p2<<<8, TPB>>>(other, W_emb, b_emb, W_ih, b_ih, W_hh, b_hh,
                         W_out, b_out, out);
    olstm_head<<<STEPS, 160>>>(W_out, b_out, out);
}